// round 14
// baseline (speedup 1.0000x reference)
#include <cuda_runtime.h>

#define BB 1024
#define TT 200

// Precomputed x-dependent halves:
// g_Xg[m][j] = b_gate[j] + sum_k X[m][k]*W_gate[k][j]   (j in [0,256))
// g_Xc[m][j] = b_cand[j] + sum_k X[m][k]*W_cand[k][j]   (j in [0,128))
__device__ float g_Xg[(size_t)BB * TT * 256];
__device__ float g_Xc[(size_t)BB * TT * 128];

typedef unsigned long long u64;

__device__ __forceinline__ u64 pack2(float a, float b) {
    u64 r; asm("mov.b64 %0,{%1,%2};" : "=l"(r) : "f"(a), "f"(b)); return r;
}
__device__ __forceinline__ u64 splat2(float a) { return pack2(a, a); }
__device__ __forceinline__ void fma2(u64& d, u64 a, u64 b) {
    asm("fma.rn.f32x2 %0,%1,%2,%0;" : "+l"(d) : "l"(a), "l"(b));
}
__device__ __forceinline__ float2 unpack2(u64 v) {
    float2 r; asm("mov.b64 {%0,%1},%2;" : "=f"(r.x), "=f"(r.y) : "l"(v)); return r;
}

__device__ __forceinline__ float sigmoid_f(float x) {
    return __fdividef(1.0f, 1.0f + __expf(-x));
}
__device__ __forceinline__ float tanh_f(float x) {
    return 1.0f - __fdividef(2.0f, __expf(2.0f * x) + 1.0f);
}

// ---------------------------------------------------------------------------
// Kernel A: Xg/Xc precompute GEMM (R12 version, measured ~400us).
// ---------------------------------------------------------------------------
__global__ __launch_bounds__(256, 2)
void precompute_kernel(const float* __restrict__ X,
                       const float* __restrict__ Wg,
                       const float* __restrict__ bg,
                       const float* __restrict__ Wc,
                       const float* __restrict__ bc)
{
    extern __shared__ float sm[];
    float* Xs = sm;              // [64][132] row-major, padded
    float* Ws = sm + 64 * 132;   // [128][128]

    const int tid = threadIdx.x;
    const int m0  = blockIdx.x * 64;

    #pragma unroll
    for (int i = 0; i < 8; i++) {
        int idx = tid + i * 256;
        int m   = idx >> 5;
        int k4  = idx & 31;
        float4 v = *(const float4*)&X[(size_t)(m0 + m) * 128 + k4 * 4];
        *(float4*)&Xs[m * 132 + k4 * 4] = v;
    }

    const int colg = tid & 31;
    const int rowg = tid >> 5;
    const int c0 = colg * 4;
    const int r0 = rowg * 8;

    for (int nt = 0; nt < 3; nt++) {
        __syncthreads();
        const float* Wsrc; int ldw, n0;
        if (nt < 2) { Wsrc = Wg; ldw = 256; n0 = nt * 128; }
        else        { Wsrc = Wc; ldw = 128; n0 = 0; }
        #pragma unroll
        for (int i = 0; i < 16; i++) {
            int idx = tid + i * 256;
            int k   = idx >> 5;
            int j4  = idx & 31;
            *(float4*)&Ws[k * 128 + j4 * 4] =
                *(const float4*)&Wsrc[(size_t)k * ldw + n0 + j4 * 4];
        }
        __syncthreads();

        u64 acc[8][2];
        #pragma unroll
        for (int r = 0; r < 8; r++) { acc[r][0] = 0ULL; acc[r][1] = 0ULL; }

        for (int k4 = 0; k4 < 32; k4++) {
            float4 xv[8];
            #pragma unroll
            for (int r = 0; r < 8; r++)
                xv[r] = *(const float4*)&Xs[(r0 + r) * 132 + k4 * 4];
            #pragma unroll
            for (int kk = 0; kk < 4; kk++) {
                ulonglong2 wv = *(const ulonglong2*)&Ws[(k4 * 4 + kk) * 128 + c0];
                #pragma unroll
                for (int r = 0; r < 8; r++) {
                    float xs = (kk == 0) ? xv[r].x : (kk == 1) ? xv[r].y
                             : (kk == 2) ? xv[r].z : xv[r].w;
                    u64 xp = splat2(xs);
                    fma2(acc[r][0], xp, wv.x);
                    fma2(acc[r][1], xp, wv.y);
                }
            }
        }

        if (nt < 2) {
            float4 bv = *(const float4*)&bg[n0 + c0];
            #pragma unroll
            for (int r = 0; r < 8; r++) {
                float2 a0 = unpack2(acc[r][0]), a1 = unpack2(acc[r][1]);
                float4 o = make_float4(a0.x + bv.x, a0.y + bv.y,
                                       a1.x + bv.z, a1.y + bv.w);
                *(float4*)&g_Xg[(size_t)(m0 + r0 + r) * 256 + n0 + c0] = o;
            }
        } else {
            float4 bv = *(const float4*)&bc[c0];
            #pragma unroll
            for (int r = 0; r < 8; r++) {
                float2 a0 = unpack2(acc[r][0]), a1 = unpack2(acc[r][1]);
                float4 o = make_float4(a0.x + bv.x, a0.y + bv.y,
                                       a1.x + bv.z, a1.y + bv.w);
                *(float4*)&g_Xc[(size_t)(m0 + r0 + r) * 128 + c0] = o;
            }
        }
    }
}

// ---------------------------------------------------------------------------
// Kernel B: GRU recurrence, weights-read-ONCE + pair-packed state.
// 128 blocks x 128 threads; block owns 8 batch rows.
// State arrays hp/rp/up are float2 "row-pair" images: xp[p][col] holds
// (val[row 2p][col], val[row 2p+1][col]), p = 0..3, PITCH = 130 float2.
//   Phase G: thread owns gate cols (2*tid, 2*tid+1), ALL 8 rows.
//            Wg read once per block per step (u64/lane, zero redundancy);
//            h pairs arrive as broadcast u128 (2 k's) -> fma2 with NO packs.
//   Phase C: thread owns cand col tid, ALL 8 rows. Wc read once.
// Epilogue stores are lane-consecutive (no transposed-store conflicts).
// ---------------------------------------------------------------------------
#define PITCH 130   // float2 units per pair-row

__global__ __launch_bounds__(128, 1)
void gru_kernel(const float* __restrict__ Wg,   // [256][256]
                const float* __restrict__ Wc,   // [256][128]
                const int*   __restrict__ seq_len,
                float* __restrict__ out)        // [1024][200][128]
{
    extern __shared__ float sm[];
    float* Wg_s = sm;                        // [128][256] h-part of W_gate
    float* Wc_s = Wg_s + 128 * 256;          // [128][128] h-part of W_cand
    float2* hp  = (float2*)(Wc_s + 128 * 128);   // [4][PITCH] h row-pairs
    float2* rp  = hp + 4 * PITCH;                // [4][PITCH] r*h row-pairs
    float2* up  = rp + 4 * PITCH;                // [4][PITCH] u row-pairs

    const int tid = threadIdx.x;
    const int b0  = blockIdx.x * 8;

    #pragma unroll
    for (int i = 0; i < 64; i++) {
        int idx = tid + i * 128;
        *(float4*)&Wg_s[idx * 4] = *(const float4*)&Wg[128 * 256 + idx * 4];
    }
    #pragma unroll
    for (int i = 0; i < 32; i++) {
        int idx = tid + i * 128;
        *(float4*)&Wc_s[idx * 4] = *(const float4*)&Wc[128 * 128 + idx * 4];
    }
    for (int i = tid; i < 4 * PITCH; i += 128) hp[i] = make_float2(0.0f, 0.0f);
    __syncthreads();

    const int gc = tid * 2;                  // gate col pair base (0..254)
    int sl[8];
    #pragma unroll
    for (int i = 0; i < 8; i++) sl[i] = seq_len[b0 + i];

    for (int t = 0; t < TT; t++) {
        // ---- Phase G --------------------------------------------------------
        // xg loads issued first; consumed only at the sigmoid (latency hidden).
        float2 xg[8];
        #pragma unroll
        for (int i = 0; i < 8; i++)
            xg[i] = *(const float2*)&g_Xg[((size_t)(b0 + i) * TT + t) * 256 + gc];

        // acc[p][c]: rows (2p,2p+1) packed in lanes, col gc+c.
        u64 acc[4][2];
        #pragma unroll
        for (int p = 0; p < 4; p++) { acc[p][0] = 0ULL; acc[p][1] = 0ULL; }

        #pragma unroll 2
        for (int k4 = 0; k4 < 32; k4++) {
            ulonglong2 ha[4], hb[4];         // ha: k4*4, k4*4+1; hb: +2, +3
            #pragma unroll
            for (int p = 0; p < 4; p++) {
                ha[p] = *(const ulonglong2*)&hp[p * PITCH + k4 * 4];
                hb[p] = *(const ulonglong2*)&hp[p * PITCH + k4 * 4 + 2];
            }
            #pragma unroll
            for (int kk = 0; kk < 4; kk++) {
                u64 wp = *(const u64*)&Wg_s[(k4 * 4 + kk) * 256 + gc];
                float2 wf = unpack2(wp);
                u64 w0 = splat2(wf.x), w1 = splat2(wf.y);
                #pragma unroll
                for (int p = 0; p < 4; p++) {
                    u64 hv = (kk == 0) ? ha[p].x : (kk == 1) ? ha[p].y
                           : (kk == 2) ? hb[p].x : hb[p].y;
                    fma2(acc[p][0], hv, w0);
                    fma2(acc[p][1], hv, w1);
                }
            }
        }

        // gates (add xg at the end; same per-output summation order).
        float g[8][2];
        #pragma unroll
        for (int p = 0; p < 4; p++) {
            float2 a0 = unpack2(acc[p][0]), a1 = unpack2(acc[p][1]);
            g[2 * p][0]     = sigmoid_f(a0.x + xg[2 * p].x);
            g[2 * p + 1][0] = sigmoid_f(a0.y + xg[2 * p + 1].x);
            g[2 * p][1]     = sigmoid_f(a1.x + xg[2 * p].y);
            g[2 * p + 1][1] = sigmoid_f(a1.y + xg[2 * p + 1].y);
        }

        if (tid < 64) {
            // r-gates (cols gc, gc+1 < 128): rp[p][col] = r * h, both cols as
            // one float4 (lane-consecutive store).
            #pragma unroll
            for (int p = 0; p < 4; p++) {
                float4 hh = *(const float4*)&hp[p * PITCH + gc];
                float4 o;
                o.x = g[2 * p][0]     * hh.x;
                o.y = g[2 * p + 1][0] * hh.y;
                o.z = g[2 * p][1]     * hh.z;
                o.w = g[2 * p + 1][1] * hh.w;
                *(float4*)&rp[p * PITCH + gc] = o;
            }
        } else {
            // u-gates (cols gc-128, gc-127).
            const int uc = gc - 128;
            #pragma unroll
            for (int p = 0; p < 4; p++) {
                float4 o;
                o.x = g[2 * p][0];
                o.y = g[2 * p + 1][0];
                o.z = g[2 * p][1];
                o.w = g[2 * p + 1][1];
                *(float4*)&up[p * PITCH + uc] = o;
            }
        }
        __syncthreads();

        // ---- Phase C: cand col tid, all 8 rows ------------------------------
        float xc[8];
        #pragma unroll
        for (int i = 0; i < 8; i++)
            xc[i] = g_Xc[((size_t)(b0 + i) * TT + t) * 128 + tid];

        u64 ac[4];
        #pragma unroll
        for (int p = 0; p < 4; p++) ac[p] = 0ULL;

        #pragma unroll 2
        for (int k4 = 0; k4 < 32; k4++) {
            ulonglong2 ra[4], rb[4];
            #pragma unroll
            for (int p = 0; p < 4; p++) {
                ra[p] = *(const ulonglong2*)&rp[p * PITCH + k4 * 4];
                rb[p] = *(const ulonglong2*)&rp[p * PITCH + k4 * 4 + 2];
            }
            #pragma unroll
            for (int kk = 0; kk < 4; kk++) {
                u64 ws = splat2(Wc_s[(k4 * 4 + kk) * 128 + tid]);
                #pragma unroll
                for (int p = 0; p < 4; p++) {
                    u64 rv = (kk == 0) ? ra[p].x : (kk == 1) ? ra[p].y
                           : (kk == 2) ? rb[p].x : rb[p].y;
                    fma2(ac[p], rv, ws);
                }
            }
        }

        #pragma unroll
        for (int p = 0; p < 4; p++) {
            float2 a = unpack2(ac[p]);
            float cv0 = tanh_f(a.x + xc[2 * p]);
            float cv1 = tanh_f(a.y + xc[2 * p + 1]);
            float2 uu = up[p * PITCH + tid];
            float2 hh = hp[p * PITCH + tid];
            float hn0 = uu.x * hh.x + (1.0f - uu.x) * cv0;
            float hn1 = uu.y * hh.y + (1.0f - uu.y) * cv1;
            bool v0 = (t < sl[2 * p]);
            bool v1 = (t < sl[2 * p + 1]);
            float2 hw;
            hw.x = v0 ? hn0 : hh.x;
            hw.y = v1 ? hn1 : hh.y;
            hp[p * PITCH + tid] = hw;
            out[((size_t)(b0 + 2 * p) * TT + t) * 128 + tid]     = v0 ? hn0 : 0.0f;
            out[((size_t)(b0 + 2 * p + 1) * TT + t) * 128 + tid] = v1 ? hn1 : 0.0f;
        }
        __syncthreads();
    }
}

// ---------------------------------------------------------------------------
extern "C" void kernel_launch(void* const* d_in, const int* in_sizes, int n_in,
                              void* d_out, int out_size)
{
    (void)in_sizes; (void)n_in; (void)out_size;
    const float* X   = (const float*)d_in[0];   // item_his_eb [1024,200,128]
    const int*   sq  = (const int*)  d_in[1];   // seq_len [1024]
    const float* Wg  = (const float*)d_in[2];   // W_gate [256,256]
    const float* bg  = (const float*)d_in[3];   // b_gate [256]
    const float* Wc  = (const float*)d_in[4];   // W_cand [256,128]
    const float* bc  = (const float*)d_in[5];   // b_cand [128]
    float* out = (float*)d_out;                 // [1024,200,128]

    const int smemA = (64 * 132 + 128 * 128) * 4;                         // 99328
    const int smemB = (128 * 256 + 128 * 128) * 4 + 3 * 4 * PITCH * 8;    // 209152
    cudaFuncSetAttribute(precompute_kernel,
                         cudaFuncAttributeMaxDynamicSharedMemorySize, smemA);
    cudaFuncSetAttribute(gru_kernel,
                         cudaFuncAttributeMaxDynamicSharedMemorySize, smemB);

    precompute_kernel<<<3200, 256, smemA>>>(X, Wg, bg, Wc, bc);
    gru_kernel<<<128, 128, smemB>>>(Wg, Wc, sq, out);
}